// round 16
// baseline (speedup 1.0000x reference)
#include <cuda_runtime.h>
#include <cuda_bf16.h>
#include <math.h>
#include <stdint.h>

#define Bb 8
#define Nn 1024
#define Ee 256
#define Hh 4
#define Uu 6
#define Oo 8
#define LAMBDA_INIT 0.63212055882855767840f
#define LOG2E 1.44269504088896340736f

typedef unsigned long long ull;

// ---------------- scratch (static device memory; no allocation) ----------------
__device__ unsigned char g_maskT[(size_t)Bb * Nn * Nn];
__device__ __nv_bfloat16 g_v_hi[(size_t)Bb * Nn * Ee];
__device__ __nv_bfloat16 g_v_lo[(size_t)Bb * Nn * Ee];
__device__ __nv_bfloat16 g_x_hi[(size_t)Bb * Nn * Ee];
__device__ __nv_bfloat16 g_x_lo[(size_t)Bb * Nn * Ee];
__device__ __nv_bfloat16 g_op_hi[(size_t)Bb * Nn * Ee];
__device__ __nv_bfloat16 g_op_lo[(size_t)Bb * Nn * Ee];
__device__ __nv_bfloat16 g_vw_hi[(size_t)Ee * Ee];
__device__ __nv_bfloat16 g_vw_lo[(size_t)Ee * Ee];
__device__ __nv_bfloat16 g_ow_hi[(size_t)Ee * Ee];
__device__ __nv_bfloat16 g_ow_lo[(size_t)Ee * Ee];
__device__ __nv_bfloat16 g_a_hi[(size_t)Bb * Hh * Nn * Nn];   // 64 MB attn bf16 hi
__device__ __nv_bfloat16 g_a_lo[(size_t)Bb * Hh * Nn * Nn];   // 64 MB attn bf16 lo
__device__ float g_beta;
__device__ int   g_mask_kind;

// ---------------- helpers ----------------
__device__ __forceinline__ ull pack2(float a, float b) {
    ull r; asm("mov.b64 %0, {%1,%2};" : "=l"(r) : "f"(a), "f"(b)); return r;
}
__device__ __forceinline__ float2 unpack2(ull v) {
    float2 r; asm("mov.b64 {%0,%1}, %2;" : "=f"(r.x), "=f"(r.y) : "l"(v)); return r;
}
__device__ __forceinline__ ull ffma2(ull a, ull b, ull c) {
    ull d; asm("fma.rn.f32x2 %0, %1, %2, %3;" : "=l"(d) : "l"(a), "l"(b), "l"(c)); return d;
}
__device__ __forceinline__ uint32_t cvt_bf16x2(float a1, float a0) {
    uint32_t r; asm("cvt.rn.bf16x2.f32 %0, %1, %2;" : "=r"(r) : "f"(a1), "f"(a0)); return r;
}
__device__ __forceinline__ float ex2f(float x) {
    float r; asm("ex2.approx.f32 %0, %1;" : "=f"(r) : "f"(x)); return r;
}
__device__ __forceinline__ uint32_t smem_u32(const void* p) {
    uint32_t a;
    asm("{ .reg .u64 t; cvta.to.shared.u64 t, %1; cvt.u32.u64 %0, t; }" : "=r"(a) : "l"(p));
    return a;
}
__device__ __forceinline__ void cp_async16(uint32_t smem_addr, const void* gmem) {
    asm volatile("cp.async.cg.shared.global [%0], [%1], 16;" :: "r"(smem_addr), "l"(gmem));
}
__device__ __forceinline__ void cp_async_commit() {
    asm volatile("cp.async.commit_group;" ::: "memory");
}
__device__ __forceinline__ void cp_async_wait0() {
    asm volatile("cp.async.wait_group 0;" ::: "memory");
}
__device__ __forceinline__ void ldmatrix_x4(uint32_t& r0, uint32_t& r1, uint32_t& r2,
                                            uint32_t& r3, uint32_t addr) {
    asm volatile("ldmatrix.sync.aligned.m8n8.x4.shared.b16 {%0,%1,%2,%3}, [%4];"
                 : "=r"(r0), "=r"(r1), "=r"(r2), "=r"(r3) : "r"(addr));
}
__device__ __forceinline__ void ldmatrix_x4_trans(uint32_t& r0, uint32_t& r1, uint32_t& r2,
                                                  uint32_t& r3, uint32_t addr) {
    asm volatile("ldmatrix.sync.aligned.m8n8.x4.trans.shared.b16 {%0,%1,%2,%3}, [%4];"
                 : "=r"(r0), "=r"(r1), "=r"(r2), "=r"(r3) : "r"(addr));
}
__device__ __forceinline__ void mma_bf16(float* c, uint32_t a0, uint32_t a1, uint32_t a2,
                                         uint32_t a3, uint32_t b0, uint32_t b1) {
    asm volatile(
        "mma.sync.aligned.m16n8k16.row.col.f32.bf16.bf16.f32 "
        "{%0,%1,%2,%3}, {%4,%5,%6,%7}, {%8,%9}, {%0,%1,%2,%3};"
        : "+f"(c[0]), "+f"(c[1]), "+f"(c[2]), "+f"(c[3])
        : "r"(a0), "r"(a1), "r"(a2), "r"(a3), "r"(b0), "r"(b1));
}

// ---------------- L1: detect mask dtype + beta ----------------
__global__ void detect_beta_kernel(const unsigned char* __restrict__ raw,
                                   const float* __restrict__ lq,
                                   const float* __restrict__ lk,
                                   float* __restrict__ beta_slot) {
    __shared__ int cnt[4];
    __shared__ float red[128];
    int t = threadIdx.x;
    if (t < 4) cnt[t] = 0;
    if (t < 128) red[t] = (t < 100) ? lq[t] * lk[t] : 0.f;
    __syncthreads();
    for (int i = t; i < 16384; i += blockDim.x)
        if (raw[i]) atomicAdd(&cnt[i & 3], 1);
    for (int st = 64; st > 0; st >>= 1) {
        if (t < st) red[t] += red[t + st];
        __syncthreads();
    }
    if (t == 0) {
        int kind;
        if (cnt[1] == 0 && cnt[2] == 0 && cnt[3] == 0) kind = 1;
        else if (cnt[0] == 0 && cnt[1] == 0)           kind = 2;
        else                                            kind = 0;
        g_mask_kind = kind;
        float lam1 = expf(red[0]);
        float beta = 1.f / (1.f + expf(-lam1 * LAMBDA_INIT));
        g_beta = beta;
        *beta_slot = beta;
    }
}

// ---------------- L2: prep = mask transpose + splits ----------------
#define NX4 ((int)((size_t)Bb * Nn * Ee / 4))
#define NW4 (Ee * Ee / 4)
#define PREP_GRID (8192 + (NX4 + 2 * NW4) / 256)

__global__ __launch_bounds__(256) void prep_kernel(const void* __restrict__ rawv,
                                                   const float* __restrict__ x,
                                                   const float* __restrict__ vw,
                                                   const float* __restrict__ ow) {
    int bid = blockIdx.x;
    if (bid < 8192) {
        __shared__ unsigned char tile[32][33];
        int xt = bid & 31, yt = (bid >> 5) & 31, b = bid >> 10;
        int i0 = xt * 32, j0 = yt * 32;
        int tx = threadIdx.x & 31, ty0 = threadIdx.x >> 5;
        int kind = g_mask_kind;
#pragma unroll
        for (int k = 0; k < 4; k++) {
            int ty = ty0 + k * 8;
            size_t src = ((size_t)b * Nn + (j0 + ty)) * Nn + (i0 + tx);
            unsigned char v;
            if (kind == 0)      v = (((const unsigned char*)rawv)[src] != 0);
            else if (kind == 1) v = (((const int*)rawv)[src] != 0);
            else                v = (((const float*)rawv)[src] != 0.f);
            tile[ty][tx] = v;
        }
        __syncthreads();
#pragma unroll
        for (int k = 0; k < 4; k++) {
            int ty = ty0 + k * 8;
            g_maskT[((size_t)b * Nn + (i0 + ty)) * Nn + (j0 + tx)] = tile[tx][ty];
        }
    } else {
        int idx = (bid - 8192) * 256 + threadIdx.x;
        const float* src;
        uint2 *hid, *lod;
        int li;
        if (idx < NX4) {
            src = x; hid = (uint2*)g_x_hi; lod = (uint2*)g_x_lo; li = idx;
        } else if (idx < NX4 + NW4) {
            src = vw; hid = (uint2*)g_vw_hi; lod = (uint2*)g_vw_lo; li = idx - NX4;
        } else {
            src = ow; hid = (uint2*)g_ow_hi; lod = (uint2*)g_ow_lo; li = idx - NX4 - NW4;
        }
        float4 v = ((const float4*)src)[li];
        uint32_t h0 = cvt_bf16x2(v.y, v.x);
        uint32_t h1 = cvt_bf16x2(v.w, v.z);
        float a0 = __uint_as_float(h0 << 16), a1 = __uint_as_float(h0 & 0xFFFF0000u);
        float a2 = __uint_as_float(h1 << 16), a3 = __uint_as_float(h1 & 0xFFFF0000u);
        uint32_t l0 = cvt_bf16x2(v.y - a1, v.x - a0);
        uint32_t l1 = cvt_bf16x2(v.w - a3, v.z - a2);
        hid[li] = make_uint2(h0, h1);
        lod[li] = make_uint2(l0, l1);
    }
}

// ---------------- gemm body (HMMA, 64x64 tile, 3 hi/lo combos) ----------------
#define GR_STR 144
#define GEMM_SMEM (4 * 64 * GR_STR)
template <int MODE>
__device__ __forceinline__ void gemm_body(
    char* sm, int bx, int by,
    const __nv_bfloat16* __restrict__ Ahi, const __nv_bfloat16* __restrict__ Alo,
    const __nv_bfloat16* __restrict__ Whi, const __nv_bfloat16* __restrict__ Wlo,
    float* __restrict__ Y, __nv_bfloat16* __restrict__ Yhi, __nv_bfloat16* __restrict__ Ylo) {
    char* sAh = sm;
    char* sAl = sm + 64 * GR_STR;
    char* sWh = sm + 2 * 64 * GR_STR;
    char* sWl = sm + 3 * 64 * GR_STR;
    const uint32_t smb = smem_u32(sm);

    const int t = threadIdx.x;
    const int wid = t >> 5, lane = t & 31;
    const int row0 = bx * 64;
    const int col0 = by * 64;
    const int mw = wid >> 1, nw = wid & 1;
    const int lr = lane & 7, quad = lane >> 3;
    const uint32_t aRow = (uint32_t)(mw * 16 + (quad & 1) * 8 + lr);
    const uint32_t aKoff = (uint32_t)((quad >> 1) * 16);
    const uint32_t bRow = (uint32_t)((quad >> 1) * 8 + lr);
    const uint32_t bKoff = (uint32_t)((quad & 1) * 16);

    float c[4][4];
#pragma unroll
    for (int nf = 0; nf < 4; nf++)
#pragma unroll
        for (int k = 0; k < 4; k++) c[nf][k] = 0.f;

    for (int kc = 0; kc < 4; kc++) {
        __syncthreads();
#pragma unroll
        for (int q = 0; q < 2; q++) {
            int idx = t + q * 256;
            int r = idx >> 3, c16 = idx & 7;
            *(uint4*)(sAh + r * GR_STR + c16 * 16) =
                ((const uint4*)(Ahi + (size_t)(row0 + r) * Ee + kc * 64))[c16];
            *(uint4*)(sAl + r * GR_STR + c16 * 16) =
                ((const uint4*)(Alo + (size_t)(row0 + r) * Ee + kc * 64))[c16];
            *(uint4*)(sWh + r * GR_STR + c16 * 16) =
                ((const uint4*)(Whi + (size_t)(col0 + r) * Ee + kc * 64))[c16];
            *(uint4*)(sWl + r * GR_STR + c16 * 16) =
                ((const uint4*)(Wlo + (size_t)(col0 + r) * Ee + kc * 64))[c16];
        }
        __syncthreads();
#pragma unroll
        for (int ks = 0; ks < 4; ks++) {
            uint32_t aBase = smb + aRow * GR_STR + ks * 32 + aKoff;
            uint32_t ah0, ah1, ah2, ah3, al0, al1, al2, al3;
            ldmatrix_x4(ah0, ah1, ah2, ah3, aBase);
            ldmatrix_x4(al0, al1, al2, al3, aBase + 64 * GR_STR);
#pragma unroll
            for (int np = 0; np < 2; np++) {
                uint32_t bBase = smb + 2 * 64 * GR_STR +
                                 (nw * 32 + np * 16 + bRow) * GR_STR + ks * 32 + bKoff;
                uint32_t bh0, bh1, bh2, bh3, bl0, bl1, bl2, bl3;
                ldmatrix_x4(bh0, bh1, bh2, bh3, bBase);
                ldmatrix_x4(bl0, bl1, bl2, bl3, bBase + 64 * GR_STR);
                float* c0 = c[np * 2];
                float* c1 = c[np * 2 + 1];
                mma_bf16(c0, ah0, ah1, ah2, ah3, bh0, bh1);
                mma_bf16(c0, ah0, ah1, ah2, ah3, bl0, bl1);
                mma_bf16(c0, al0, al1, al2, al3, bh0, bh1);
                mma_bf16(c1, ah0, ah1, ah2, ah3, bh2, bh3);
                mma_bf16(c1, ah0, ah1, ah2, ah3, bl2, bl3);
                mma_bf16(c1, al0, al1, al2, al3, bh2, bh3);
            }
        }
    }

    int r0 = row0 + mw * 16 + (lane >> 2);
    int colb = col0 + nw * 32 + (lane & 3) * 2;
#pragma unroll
    for (int nf = 0; nf < 4; nf++) {
        int col = colb + nf * 8;
        if (MODE == 0) {
            *(float2*)(Y + (size_t)r0 * Ee + col) = make_float2(c[nf][0], c[nf][1]);
            *(float2*)(Y + (size_t)(r0 + 8) * Ee + col) = make_float2(c[nf][2], c[nf][3]);
        } else {
            uint32_t h0 = cvt_bf16x2(c[nf][1], c[nf][0]);
            float e0 = __uint_as_float(h0 << 16), e1 = __uint_as_float(h0 & 0xFFFF0000u);
            uint32_t l0 = cvt_bf16x2(c[nf][1] - e1, c[nf][0] - e0);
            uint32_t h1 = cvt_bf16x2(c[nf][3], c[nf][2]);
            float e2 = __uint_as_float(h1 << 16), e3 = __uint_as_float(h1 & 0xFFFF0000u);
            uint32_t l1 = cvt_bf16x2(c[nf][3] - e3, c[nf][2] - e2);
            ((uint32_t*)Yhi)[((size_t)r0 * Ee + col) >> 1] = h0;
            ((uint32_t*)Ylo)[((size_t)r0 * Ee + col) >> 1] = l0;
            ((uint32_t*)Yhi)[((size_t)(r0 + 8) * Ee + col) >> 1] = h1;
            ((uint32_t*)Ylo)[((size_t)(r0 + 8) * Ee + col) >> 1] = l1;
        }
    }
}

// ---------------- stats2 body: scores once -> l -> attn fp32 + A bf16 hi/lo ----------------
__device__ __forceinline__ void stats2_body(char* sm, int i, int b,
                                            const float* __restrict__ u,
                                            const float* __restrict__ u_w,
                                            const float* __restrict__ u_b,
                                            float* __restrict__ attn_out) {
    ull* s_w2 = (ull*)sm;
    ull* s_b2 = (ull*)(sm + 384);
    float* s_red = (float*)(sm + 448);
    float* s_l = (float*)(sm + 448 + 288);
    int t = threadIdx.x;
    if (t < 48) { float w = u_w[t] * LOG2E; s_w2[t] = pack2(w, w); }
    if (t < 8)  { float bb = u_b[t] * LOG2E; s_b2[t] = pack2(bb, bb); }
    __syncthreads();

    int j0 = t * 4;
    unsigned mword = *(const unsigned*)(g_maskT + ((size_t)b * Nn + i) * Nn + j0);
    bool m0 = (mword & 0xFFu) != 0, m1 = ((mword >> 8) & 0xFFu) != 0;
    bool m2 = ((mword >> 16) & 0xFFu) != 0, m3 = ((mword >> 24) & 0xFFu) != 0;

    ulonglong2 u2[Uu];
#pragma unroll
    for (int c = 0; c < Uu; c++)
        u2[c] = __ldcs((const ulonglong2*)(u + ((size_t)(b * Uu + c) * Nn + i) * Nn + j0));

    float e[Oo][4];
    float l[Oo];
#pragma unroll
    for (int o = 0; o < Oo; o++) {
        ull sa = s_b2[o], sb = s_b2[o];
#pragma unroll
        for (int c = 0; c < Uu; c++) {
            sa = ffma2(s_w2[o * Uu + c], u2[c].x, sa);
            sb = ffma2(s_w2[o * Uu + c], u2[c].y, sb);
        }
        float2 f0 = unpack2(sa), f1 = unpack2(sb);
        e[o][0] = m0 ? 0.f : ex2f(f0.x);
        e[o][1] = m1 ? 0.f : ex2f(f0.y);
        e[o][2] = m2 ? 0.f : ex2f(f1.x);
        e[o][3] = m3 ? 0.f : ex2f(f1.y);
        l[o] = (e[o][0] + e[o][1]) + (e[o][2] + e[o][3]);
    }
#pragma unroll
    for (int o = 0; o < Oo; o++)
#pragma unroll
        for (int st = 16; st > 0; st >>= 1)
            l[o] += __shfl_xor_sync(0xFFFFFFFFu, l[o], st);
    int w = t >> 5, lane = t & 31;
    if (lane == 0) {
#pragma unroll
        for (int o = 0; o < Oo; o++) s_red[o * 9 + w] = l[o];
    }
    __syncthreads();
    if (t < 8) {
        float s = 0.f;
#pragma unroll
        for (int w2 = 0; w2 < 8; w2++) s += s_red[t * 9 + w2];
        s_l[t] = 1.0f / s;
    }
    __syncthreads();

    const float beta = g_beta;
#pragma unroll
    for (int h = 0; h < Hh; h++) {
        float rl0 = s_l[2 * h], rl1 = s_l[2 * h + 1];
        float a0 = e[2 * h][0] * rl0 - beta * e[2 * h + 1][0] * rl1;
        float a1 = e[2 * h][1] * rl0 - beta * e[2 * h + 1][1] * rl1;
        float a2 = e[2 * h][2] * rl0 - beta * e[2 * h + 1][2] * rl1;
        float a3 = e[2 * h][3] * rl0 - beta * e[2 * h + 1][3] * rl1;
        size_t base = ((size_t)(b * Hh + h) * Nn + i) * Nn + j0;
        __stcs((float4*)(attn_out + base), make_float4(a0, a1, a2, a3));
        uint32_t hA = cvt_bf16x2(a1, a0);
        uint32_t hB = cvt_bf16x2(a3, a2);
        float e0 = __uint_as_float(hA << 16);
        float e1 = __uint_as_float(hA & 0xFFFF0000u);
        float e2 = __uint_as_float(hB << 16);
        float e3 = __uint_as_float(hB & 0xFFFF0000u);
        uint32_t lA = cvt_bf16x2(a1 - e1, a0 - e0);
        uint32_t lB = cvt_bf16x2(a3 - e3, a2 - e2);
        __stcs((uint2*)((uint32_t*)g_a_hi + (base >> 1)), make_uint2(hA, hB));
        __stcs((uint2*)((uint32_t*)g_a_lo + (base >> 1)), make_uint2(lA, lB));
    }
}

// ---------------- L3: gemm<1> + stats2 ----------------
__global__ __launch_bounds__(256) void gemm1_stats_kernel(const float* __restrict__ u,
                                                          const float* __restrict__ u_w,
                                                          const float* __restrict__ u_b,
                                                          float* __restrict__ attn_out) {
    __shared__ __align__(16) char sm[GEMM_SMEM];
    int bid = blockIdx.x;
    if (bid < 512) {
        gemm_body<1>(sm, bid & 127, bid >> 7,
                     g_x_hi, g_x_lo, g_vw_hi, g_vw_lo, nullptr, g_v_hi, g_v_lo);
    } else {
        int sid = bid - 512;
        stats2_body(sm, sid & 1023, sid >> 10, u, u_w, u_b, attn_out);
    }
}

// ---------------- L5: out projection ----------------
__global__ __launch_bounds__(256) void gemm0_kernel(float* __restrict__ Y) {
    __shared__ __align__(16) char sm[GEMM_SMEM];
    gemm_body<0>(sm, blockIdx.x, blockIdx.y,
                 g_op_hi, g_op_lo, g_ow_hi, g_ow_lo, Y, nullptr, nullptr);
}

// ---------------- L4: av — HMMA GEMM, 64-row strips, 3 blocks/SM ----------------
// grid (16, 32), 256 threads (8 warps: 4 m-groups x 2 n-halves), j tiles of 64, double buffered.
#define AV_RS   144
#define AV_AH   0
#define AV_AL   9216           // 64 x 144
#define AV_VH   18432
#define AV_VL   27648
#define AV_BUF  36864
#define AV_TOT  (2 * 36864)    // 73728

__global__ __launch_bounds__(256) void av_kernel() {
    extern __shared__ char smc[];
    const uint32_t smem_base = smem_u32(smc);

    const int t = threadIdx.x;
    const int wid = t >> 5;
    const int lane = t & 31;
    const int i0 = blockIdx.x * 64;
    const int bh = blockIdx.y;
    const int b = bh >> 2, h = bh & 3;

    const __nv_bfloat16* Ahg = g_a_hi + ((size_t)bh * Nn + i0) * Nn;
    const __nv_bfloat16* Alg = g_a_lo + ((size_t)bh * Nn + i0) * Nn;
    const __nv_bfloat16* Vhg = g_v_hi + (size_t)b * Nn * Ee + h * 64;
    const __nv_bfloat16* Vlg = g_v_lo + (size_t)b * Nn * Ee + h * 64;

    const int mw = wid >> 1;              // 0..3, rows mw*16
    const int nw = wid & 1;               // cols nw*32
    const int lg = lane >> 3, lr = lane & 7;
    const uint32_t a_row = (uint32_t)(mw * 16 + (lg & 1) * 8 + lr);
    const uint32_t a_kh = (uint32_t)(lg >> 1);
    const uint32_t b_krow = (uint32_t)((lg & 1) * 8 + lr);
    const uint32_t b_ncol = (uint32_t)(nw * 32 + (lg >> 1) * 8);

    float c[4][4];
#pragma unroll
    for (int nf = 0; nf < 4; nf++)
#pragma unroll
        for (int k = 0; k < 4; k++) c[nf][k] = 0.f;

    auto cp_tile = [&](int jt, uint32_t buf) {
        // A hi/lo: 64 rows x 8 chunks each -> 512 per type; 2 per thread per type
#pragma unroll
        for (int q = 0; q < 2; q++) {
            int idx = t + q * 256;
            int r = idx >> 3, ck = idx & 7;
            cp_async16(buf + AV_AH + r * AV_RS + ck * 16,
                       Ahg + (size_t)r * Nn + jt * 64 + ck * 8);
            cp_async16(buf + AV_AL + r * AV_RS + ck * 16,
                       Alg + (size_t)r * Nn + jt * 64 + ck * 8);
            cp_async16(buf + AV_VH + r * AV_RS + ck * 16,
                       Vhg + (size_t)(jt * 64 + r) * Ee + ck * 8);
            cp_async16(buf + AV_VL + r * AV_RS + ck * 16,
                       Vlg + (size_t)(jt * 64 + r) * Ee + ck * 8);
        }
        cp_async_commit();
    };

    // prologue
    cp_tile(0, smem_base);
    cp_async_wait0();
    __syncthreads();

    for (int jt = 0; jt < 16; jt++) {
        const uint32_t bufC = smem_base + (jt & 1) * AV_BUF;
        const bool has_next = (jt < 15);
        if (has_next) cp_tile(jt + 1, smem_base + ((jt + 1) & 1) * AV_BUF);

#pragma unroll
        for (int ks = 0; ks < 4; ks++) {
            uint32_t aAddr = bufC + AV_AH + a_row * AV_RS + ks * 32 + a_kh * 16;
            uint32_t ah0, ah1, ah2, ah3, al0, al1, al2, al3;
            ldmatrix_x4(ah0, ah1, ah2, ah3, aAddr);
            ldmatrix_x4(al0, al1, al2, al3, aAddr + (AV_AL - AV_AH));
#pragma unroll
            for (int np = 0; np < 2; np++) {
                uint32_t bAddr = bufC + AV_VH + (ks * 16 + b_krow) * AV_RS +
                                 (np * 16 + b_ncol) * 2;
                uint32_t bh0, bh1, bh2, bh3, bl0, bl1, bl2, bl3;
                ldmatrix_x4_trans(bh0, bh1, bh2, bh3, bAddr);
                ldmatrix_x4_trans(bl0, bl1, bl2, bl3, bAddr + (AV_VL - AV_VH));
                float* c0 = c[np * 2];
                float* c1 = c[np * 2 + 1];
                mma_bf16(c0, ah0, ah1, ah2, ah3, bh0, bh1);
                mma_bf16(c0, ah0, ah1, ah2, ah3, bl0, bl1);
                mma_bf16(c0, al0, al1, al2, al3, bh0, bh1);
                mma_bf16(c1, ah0, ah1, ah2, ah3, bh2, bh3);
                mma_bf16(c1, ah0, ah1, ah2, ah3, bl2, bl3);
                mma_bf16(c1, al0, al1, al2, al3, bh2, bh3);
            }
        }

        if (has_next) cp_async_wait0();
        __syncthreads();
    }

    // epilogue: C -> g_op bf16 hi/lo
    {
        int r = lane >> 2, cq = lane & 3;
        int go0 = i0 + mw * 16 + r;
        int go1 = go0 + 8;
#pragma unroll
        for (int nf = 0; nf < 4; nf++) {
            int col = h * 64 + nw * 32 + nf * 8 + cq * 2;
            uint32_t h0 = cvt_bf16x2(c[nf][1], c[nf][0]);
            float e0 = __uint_as_float(h0 << 16), e1 = __uint_as_float(h0 & 0xFFFF0000u);
            uint32_t l0 = cvt_bf16x2(c[nf][1] - e1, c[nf][0] - e0);
            uint32_t h1 = cvt_bf16x2(c[nf][3], c[nf][2]);
            float e2 = __uint_as_float(h1 << 16), e3 = __uint_as_float(h1 & 0xFFFF0000u);
            uint32_t l1 = cvt_bf16x2(c[nf][3] - e3, c[nf][2] - e2);
            ((uint32_t*)g_op_hi)[(((size_t)b * Nn + go0) * Ee + col) >> 1] = h0;
            ((uint32_t*)g_op_lo)[(((size_t)b * Nn + go0) * Ee + col) >> 1] = l0;
            ((uint32_t*)g_op_hi)[(((size_t)b * Nn + go1) * Ee + col) >> 1] = h1;
            ((uint32_t*)g_op_lo)[(((size_t)b * Nn + go1) * Ee + col) >> 1] = l1;
        }
    }
}

// ---------------- launch ----------------
extern "C" void kernel_launch(void* const* d_in, const int* in_sizes, int n_in,
                              void* d_out, int out_size) {
    const float* x     = (const float*)d_in[0];
    const float* u     = (const float*)d_in[1];
    const void*  umask = d_in[2];
    const float* v_w   = (const float*)d_in[3];
    const float* out_w = (const float*)d_in[4];
    const float* u_w   = (const float*)d_in[5];
    const float* u_b   = (const float*)d_in[6];
    const float* lq    = (const float*)d_in[7];
    const float* lk    = (const float*)d_in[8];

    float* out = (float*)d_out;
    const size_t OUT_ELEMS  = (size_t)Bb * Nn * Ee;
    const size_t ATTN_ELEMS = (size_t)Bb * Hh * Nn * Nn;
    float* attn_out  = out + OUT_ELEMS;
    float* beta_slot = out + OUT_ELEMS + ATTN_ELEMS;

    static bool attr_set = false;
    if (!attr_set) {
        cudaFuncSetAttribute(av_kernel, cudaFuncAttributeMaxDynamicSharedMemorySize, AV_TOT);
        attr_set = true;
    }

    detect_beta_kernel<<<1, 256>>>((const unsigned char*)umask, lq, lk, beta_slot);   // #1
    prep_kernel<<<PREP_GRID, 256>>>(umask, x, v_w, out_w);                             // #2
    gemm1_stats_kernel<<<512 + Nn * Bb, 256>>>(u, u_w, u_b, attn_out);                 // #3
    av_kernel<<<dim3(16, 32), 256, AV_TOT>>>();                                        // #4 (profiled)
    gemm0_kernel<<<dim3(128, 4), 256>>>(out);                                          // #5
    (void)in_sizes; (void)n_in; (void)out_size;
}